// round 1
// baseline (speedup 1.0000x reference)
#include <cuda_runtime.h>
#include <cstdint>
#include <cstddef>

#define T_STEPS 500
#define BATCH   128
#define NIN     300
#define EDIM    128
#define CDIM    128
#define UDIM    64
#define FDIM    4
#define G3E     384      // 3*E == 3*C
#define CLIPV   5.0f

// ---------------- scratch (device globals; no runtime allocation) ----------------
__device__ float g_xpf[(size_t)T_STEPS * BATCH * G3E];       // 98.3 MB
__device__ float g_xpb[(size_t)T_STEPS * BATCH * G3E];       // 98.3 MB
__device__ float g_g  [(size_t)T_STEPS * BATCH * 2 * EDIM];  // 65.5 MB
__device__ float g_cp [(size_t)T_STEPS * BATCH * G3E];       // 98.3 MB

// ---------------------------------------------------------------------------------
// Generic SGEMM: C[64000,384] = A @ W^T + bias
//   A rows are (t,b) with optional time reversal of the source row.
//   A is optionally a split source: k<K0 from A0 (row stride K0), else A1.
//   W is [384, K0+K1] row-major.  Block tile 128x128x8, 256 threads, 8x8 micro.
// ---------------------------------------------------------------------------------
__global__ __launch_bounds__(256) void sgemm_bias(
    const float* __restrict__ A0, int K0,
    const float* __restrict__ A1, int K1,
    const float* __restrict__ W, const float* __restrict__ bias,
    float* __restrict__ C, int reverse)
{
    const int Ktot = K0 + K1;
    const int tb = blockIdx.x;           // time block == timestep (BM == BATCH)
    const int n0 = blockIdx.y * 128;

    __shared__ __align__(16) float As[8][132];
    __shared__ __align__(16) float Bs[8][132];

    const int tid = threadIdx.x;
    const int lr = tid >> 1;             // 0..127 (row within tile)
    const int lk = (tid & 1) * 4;        // 0 or 4
    const int srow = reverse ? ((T_STEPS - 1 - tb) * BATCH + lr)
                             : (tb * BATCH + lr);
    const int wrow = n0 + lr;

    const int ty = tid >> 4;             // 0..15
    const int tx = tid & 15;             // 0..15

    float acc[8][8];
    #pragma unroll
    for (int i = 0; i < 8; i++)
        #pragma unroll
        for (int j = 0; j < 8; j++) acc[i][j] = 0.f;

    for (int k0 = 0; k0 < Ktot; k0 += 8) {
        #pragma unroll
        for (int q = 0; q < 4; q++) {
            int kg = k0 + lk + q;
            float va = 0.f, vb = 0.f;
            if (kg < Ktot) {
                va = (kg < K0) ? A0[(size_t)srow * K0 + kg]
                               : A1[(size_t)srow * K1 + (kg - K0)];
                vb = W[(size_t)wrow * Ktot + kg];
            }
            As[lk + q][lr] = va;
            Bs[lk + q][lr] = vb;
        }
        __syncthreads();
        #pragma unroll
        for (int kk = 0; kk < 8; kk++) {
            float4 a0v = *(const float4*)&As[kk][ty * 8];
            float4 a1v = *(const float4*)&As[kk][ty * 8 + 4];
            float4 b0v = *(const float4*)&Bs[kk][tx * 8];
            float4 b1v = *(const float4*)&Bs[kk][tx * 8 + 4];
            float av[8] = {a0v.x, a0v.y, a0v.z, a0v.w, a1v.x, a1v.y, a1v.z, a1v.w};
            float bv[8] = {b0v.x, b0v.y, b0v.z, b0v.w, b1v.x, b1v.y, b1v.z, b1v.w};
            #pragma unroll
            for (int i = 0; i < 8; i++)
                #pragma unroll
                for (int j = 0; j < 8; j++)
                    acc[i][j] += av[i] * bv[j];
        }
        __syncthreads();
    }

    #pragma unroll
    for (int i = 0; i < 8; i++) {
        size_t row = (size_t)tb * BATCH + ty * 8 + i;
        float* cp = C + row * G3E + n0 + tx * 8;
        const float* bp = bias + n0 + tx * 8;
        #pragma unroll
        for (int j = 0; j < 8; j++) cp[j] = acc[i][j] + bp[j];
    }
}

__device__ __forceinline__ float sigmf(float x) {
    return 1.0f / (1.0f + __expf(-x));
}

// ---------------------------------------------------------------------------------
// Encoder bidirectional GRU scan.
// grid = 256 blocks: blocks [0,128) forward (one batch row each), [128,256) backward.
// 384 threads; thread j holds Whh row j (128 floats) in registers.
// Writes clipped g into g_g at the ORIGINAL timeline position.
// ---------------------------------------------------------------------------------
__global__ __launch_bounds__(384, 1) void enc_scan(
    const float* __restrict__ Whh_f, const float* __restrict__ bhh_f,
    const float* __restrict__ Whh_b, const float* __restrict__ bhh_b,
    const float* __restrict__ enc_init)
{
    const int j = threadIdx.x;
    const int dir = blockIdx.x >> 7;
    const int b = blockIdx.x & 127;
    const float* Whh = dir ? Whh_b : Whh_f;
    const float* bhh = dir ? bhh_b : bhh_f;
    const float* xp = dir ? g_xpb : g_xpf;

    float w[128];
    #pragma unroll
    for (int k = 0; k < 128; k++) w[k] = Whh[j * 128 + k];
    const float bh = bhh[j];

    __shared__ __align__(16) float h_s[128];
    __shared__ float hh_s[384];
    if (j < 128) h_s[j] = enc_init[dir * 128 + j];
    __syncthreads();

    for (int t = 0; t < T_STEPS; t++) {
        const float* xr = xp + ((size_t)t * BATCH + b) * G3E;
        float pr = 0.f, pz = 0.f, pn = 0.f;
        if (j < 128) { pr = xr[j]; pz = xr[128 + j]; pn = xr[256 + j]; }

        float a0 = 0.f, a1 = 0.f, a2 = 0.f, a3 = 0.f;
        const float4* h4 = (const float4*)h_s;
        #pragma unroll
        for (int kk = 0; kk < 32; kk++) {
            float4 hv = h4[kk];
            a0 += w[4 * kk + 0] * hv.x;
            a1 += w[4 * kk + 1] * hv.y;
            a2 += w[4 * kk + 2] * hv.z;
            a3 += w[4 * kk + 3] * hv.w;
        }
        hh_s[j] = bh + ((a0 + a1) + (a2 + a3));
        __syncthreads();

        if (j < 128) {
            float r = sigmf(pr + hh_s[j]);
            float z = sigmf(pz + hh_s[128 + j]);
            float n = tanhf(pn + r * hh_s[256 + j]);
            float h = (1.f - z) * n + z * h_s[j];
            h_s[j] = h;
            float gc = fminf(fmaxf(h, -CLIPV), CLIPV);
            int tt = dir ? (T_STEPS - 1 - t) : t;
            g_g[((size_t)tt * BATCH + b) * (2 * EDIM) + dir * EDIM + j] = gc;
        }
        __syncthreads();
    }
}

// ---------------------------------------------------------------------------------
// Controller GRU + latent sample + spike/calcium generator.
// grid = 128 blocks (one batch row), 384 threads.
// ctrl_Whh rows in registers; W_mu/W_lv and W_spk in (padded) dynamic SMEM.
// SMEM layout (floats):
//   wml   @ 0      : 128 rows x 132 (row j<64 = W_mu[j], else W_lv[j-64])
//   wspk  @ 16896  : 300 rows x 76
//   h_s   @ 39696  : 128
//   hh_s  @ 39824  : 384
//   mlv   @ 40208  : 128
//   gen   @ 40336  : 68
//   bml   @ 40404  : 128
//   bsp   @ 40532  : 300
// total 40832 floats = 163328 bytes
// ---------------------------------------------------------------------------------
#define CTRL_SMEM_FLOATS 40832
#define CTRL_SMEM_BYTES  (CTRL_SMEM_FLOATS * 4)

__global__ __launch_bounds__(384, 1) void ctrl_scan(
    const float* __restrict__ factors, const float* __restrict__ eps,
    const float* __restrict__ Whh, const float* __restrict__ bhh,
    const float* __restrict__ cinit,
    const float* __restrict__ W_mu, const float* __restrict__ b_mu,
    const float* __restrict__ W_lv, const float* __restrict__ b_lv,
    const float* __restrict__ W_spk, const float* __restrict__ b_spk,
    const float* __restrict__ gain_p, const float* __restrict__ biasp_p,
    const float* __restrict__ logtau_p,
    float* __restrict__ out)
{
    extern __shared__ __align__(16) float sm[];
    float* wml  = sm;
    float* wspk = sm + 16896;
    float* h_s  = sm + 39696;
    float* hh_s = sm + 39824;
    float* mlv  = sm + 40208;
    float* gen  = sm + 40336;
    float* bml  = sm + 40404;
    float* bsp  = sm + 40532;

    const int j = threadIdx.x;
    const int b = blockIdx.x;

    float w[128];
    #pragma unroll
    for (int k = 0; k < 128; k++) w[k] = Whh[j * 128 + k];
    const float bh = bhh[j];

    for (int idx = j; idx < 128 * 128; idx += 384) {
        int r = idx >> 7, k = idx & 127;
        wml[r * 132 + k] = (r < 64) ? W_mu[r * 128 + k] : W_lv[(r - 64) * 128 + k];
    }
    for (int idx = j; idx < 300 * 68; idx += 384) {
        int r = idx / 68, k = idx - r * 68;
        wspk[r * 76 + k] = W_spk[idx];
    }
    if (j < 128) { bml[j] = (j < 64) ? b_mu[j] : b_lv[j - 64]; h_s[j] = cinit[j]; }
    if (j < 300) bsp[j] = b_spk[j];

    const float gain  = gain_p[0];
    const float biasp = biasp_p[0];
    const float decay = 1.f - expf(-logtau_p[0]);
    float cal = 0.f;
    __syncthreads();

    const float4* h4 = (const float4*)h_s;

    for (int t = 0; t < T_STEPS; t++) {
        size_t row = (size_t)t * BATCH + b;
        const float* cpr = g_cp + row * G3E;
        float pr = 0.f, pz = 0.f, pn = 0.f, ev = 0.f, fv = 0.f;
        if (j < 128) { pr = cpr[j]; pz = cpr[128 + j]; pn = cpr[256 + j]; }
        if (j < UDIM) ev = eps[row * UDIM + j];
        else if (j < UDIM + FDIM) fv = factors[row * FDIM + (j - UDIM)];

        // hh = Whh @ h + bhh
        float a0 = 0.f, a1 = 0.f, a2 = 0.f, a3 = 0.f;
        #pragma unroll
        for (int kk = 0; kk < 32; kk++) {
            float4 hv = h4[kk];
            a0 += w[4 * kk + 0] * hv.x;
            a1 += w[4 * kk + 1] * hv.y;
            a2 += w[4 * kk + 2] * hv.z;
            a3 += w[4 * kk + 3] * hv.w;
        }
        hh_s[j] = bh + ((a0 + a1) + (a2 + a3));
        __syncthreads();

        // gates, clip
        if (j < 128) {
            float r = sigmf(pr + hh_s[j]);
            float z = sigmf(pz + hh_s[128 + j]);
            float n = tanhf(pn + r * hh_s[256 + j]);
            float h = (1.f - z) * n + z * h_s[j];
            h = fminf(fmaxf(h, -CLIPV), CLIPV);
            h_s[j] = h;
        }
        __syncthreads();

        // mu (j<64) / lv (64<=j<128)
        if (j < 128) {
            float m0 = 0.f, m1 = 0.f, m2 = 0.f, m3 = 0.f;
            const float4* wr = (const float4*)&wml[j * 132];
            #pragma unroll
            for (int kk = 0; kk < 32; kk++) {
                float4 wv = wr[kk];
                float4 hv = h4[kk];
                m0 += wv.x * hv.x; m1 += wv.y * hv.y;
                m2 += wv.z * hv.z; m3 += wv.w * hv.w;
            }
            mlv[j] = bml[j] + ((m0 + m1) + (m2 + m3));
        }
        __syncthreads();

        // u = mu + exp(0.5 lv) * eps ; gen = [u, f]
        if (j < UDIM) gen[j] = mlv[j] + __expf(0.5f * mlv[UDIM + j]) * ev;
        else if (j < UDIM + FDIM) gen[j] = fv;
        __syncthreads();

        // spike + calcium
        if (j < NIN) {
            float s0 = 0.f, s1 = 0.f, s2 = 0.f, s3 = 0.f;
            const float4* wr = (const float4*)&wspk[j * 76];
            const float4* g4 = (const float4*)gen;
            #pragma unroll
            for (int kk = 0; kk < 17; kk++) {
                float4 wv = wr[kk];
                float4 gv = g4[kk];
                s0 += wv.x * gv.x; s1 += wv.y * gv.y;
                s2 += wv.z * gv.z; s3 += wv.w * gv.w;
            }
            float logit = bsp[j] + ((s0 + s1) + (s2 + s3));
            float spike = fmaxf(__expf(logit) - 1.f, 0.f);
            cal = cal * decay + gain * spike + biasp;
            out[row * NIN + j] = cal;
        }
    }
}

// ---------------------------------------------------------------------------------
extern "C" void kernel_launch(void* const* d_in, const int* in_sizes, int n_in,
                              void* d_out, int out_size)
{
    (void)in_sizes; (void)n_in; (void)out_size;
    const float* x       = (const float*)d_in[0];
    const float* factors = (const float*)d_in[1];
    const float* eps     = (const float*)d_in[2];
    const float* eWihf   = (const float*)d_in[3];
    const float* eWhhf   = (const float*)d_in[4];
    const float* ebihf   = (const float*)d_in[5];
    const float* ebhhf   = (const float*)d_in[6];
    const float* eWihb   = (const float*)d_in[7];
    const float* eWhhb   = (const float*)d_in[8];
    const float* ebihb   = (const float*)d_in[9];
    const float* ebhhb   = (const float*)d_in[10];
    const float* einit   = (const float*)d_in[11];
    const float* cWih    = (const float*)d_in[12];
    const float* cWhh    = (const float*)d_in[13];
    const float* cbih    = (const float*)d_in[14];
    const float* cbhh    = (const float*)d_in[15];
    const float* cinit   = (const float*)d_in[16];
    const float* Wmu     = (const float*)d_in[17];
    const float* bmu     = (const float*)d_in[18];
    const float* Wlv     = (const float*)d_in[19];
    const float* blv     = (const float*)d_in[20];
    const float* Wspk    = (const float*)d_in[21];
    const float* bspk    = (const float*)d_in[22];
    const float* gain    = (const float*)d_in[23];
    const float* bp      = (const float*)d_in[24];
    const float* ltau    = (const float*)d_in[25];
    float* out = (float*)d_out;

    float *xpf, *xpb, *gg, *cp;
    cudaGetSymbolAddress((void**)&xpf, g_xpf);
    cudaGetSymbolAddress((void**)&xpb, g_xpb);
    cudaGetSymbolAddress((void**)&gg,  g_g);
    cudaGetSymbolAddress((void**)&cp,  g_cp);

    cudaFuncSetAttribute(ctrl_scan, cudaFuncAttributeMaxDynamicSharedMemorySize,
                         CTRL_SMEM_BYTES);

    dim3 gemm_grid(T_STEPS, G3E / 128);

    // xp_f = x @ enc_Wih_f^T + b ; xp_b = x[::-1] @ enc_Wih_b^T + b
    sgemm_bias<<<gemm_grid, 256>>>(x, NIN, nullptr, 0, eWihf, ebihf, xpf, 0);
    sgemm_bias<<<gemm_grid, 256>>>(x, NIN, nullptr, 0, eWihb, ebihb, xpb, 1);

    // bidirectional encoder scan -> g (clipped, original timeline)
    enc_scan<<<256, 384>>>(eWhhf, ebhhf, eWhhb, ebhhb, einit);

    // cp = [g, x] @ ctrl_Wih^T + b
    sgemm_bias<<<gemm_grid, 256>>>(gg, 2 * EDIM, x, NIN, cWih, cbih, cp, 0);

    // controller scan -> calcium (d_out)
    ctrl_scan<<<128, 384, CTRL_SMEM_BYTES>>>(factors, eps, cWhh, cbhh, cinit,
                                             Wmu, bmu, Wlv, blv, Wspk, bspk,
                                             gain, bp, ltau, out);
}

// round 5
// speedup vs baseline: 1.3991x; 1.3991x over previous
#include <cuda_runtime.h>
#include <cuda_bf16.h>
#include <cstdint>
#include <cstddef>

#define T_STEPS 500
#define BATCH   128
#define NIN     300
#define EDIM    128
#define CDIM    128
#define UDIM    64
#define FDIM    4
#define G3E     384      // 3*E == 3*C
#define CLIPV   5.0f

// ---------------- scratch (device globals; no runtime allocation) ----------------
__device__ float g_xpf[(size_t)T_STEPS * BATCH * G3E];
__device__ float g_xpb[(size_t)T_STEPS * BATCH * G3E];
__device__ float g_g  [(size_t)T_STEPS * BATCH * 2 * EDIM];
__device__ float g_cp [(size_t)T_STEPS * BATCH * G3E];

// bf16 hi/lo pre-converted operands (uint2-typed for guaranteed 8B alignment)
#define XN4   (T_STEPS * BATCH * NIN / 4)          // 4,800,000
#define GN4   (T_STEPS * BATCH * 2 * EDIM / 4)     // 4,096,000
#define WFN4  (G3E * NIN / 4)                      // 28,800
#define WCN4  (G3E * (2 * EDIM + NIN) / 4)         // 53,376
__device__ uint2 g_xhi[XN4],  g_xlo[XN4];
__device__ uint2 g_ghi[GN4],  g_glo[GN4];
__device__ uint2 g_wfhi[WFN4], g_wflo[WFN4];
__device__ uint2 g_wbhi[WFN4], g_wblo[WFN4];
__device__ uint2 g_wchi[WCN4], g_wclo[WCN4];

// =================================================================================
// fp32 -> bf16 (hi, lo) split conversion, vectorized x4
// =================================================================================
__device__ __forceinline__ uint32_t pack2(__nv_bfloat16 a, __nv_bfloat16 b) {
    return ((uint32_t)__bfloat16_as_ushort(b) << 16) | __bfloat16_as_ushort(a);
}

__global__ __launch_bounds__(256) void conv_split(
    const float4* __restrict__ src, uint2* __restrict__ hi, uint2* __restrict__ lo, int n4)
{
    int i = blockIdx.x * 256 + threadIdx.x;
    if (i >= n4) return;
    float4 v = src[i];
    __nv_bfloat16 h0 = __float2bfloat16_rn(v.x);
    __nv_bfloat16 h1 = __float2bfloat16_rn(v.y);
    __nv_bfloat16 h2 = __float2bfloat16_rn(v.z);
    __nv_bfloat16 h3 = __float2bfloat16_rn(v.w);
    hi[i] = make_uint2(pack2(h0, h1), pack2(h2, h3));
    __nv_bfloat16 l0 = __float2bfloat16_rn(v.x - __bfloat162float(h0));
    __nv_bfloat16 l1 = __float2bfloat16_rn(v.y - __bfloat162float(h1));
    __nv_bfloat16 l2 = __float2bfloat16_rn(v.z - __bfloat162float(h2));
    __nv_bfloat16 l3 = __float2bfloat16_rn(v.w - __bfloat162float(h3));
    lo[i] = make_uint2(pack2(l0, l1), pack2(l2, l3));
}

// =================================================================================
// Tensor-core GEMM via portable warp mma (bf16 split-2, 3 passes, fp32 accum)
//   C[64000,384] = A @ W^T + bias ; CTA tile 128(M=one timestep) x 128(N), BK=64
//   8 warps: 4(m) x 2(n) -> warp tile 32x64. K-major smem tiles, 72-b16 row stride.
// =================================================================================
#define BKT 64
#define TPAD 72                       // b16 per smem tile row (conflict-free for ldmatrix)
#define TILE_B (128 * TPAD * 2)       // 18432 bytes per tile

#define SMG_AHI 1024
#define SMG_ALO (SMG_AHI + TILE_B)
#define SMG_BHI (SMG_ALO + TILE_B)
#define SMG_BLO (SMG_BHI + TILE_B)
#define GEMM_SMEM (SMG_BLO + TILE_B)  // 74752 ; stage (128x132 f32 = 67584B) reuses 1024+

__device__ __forceinline__ uint32_t smem_u32(const void* p) {
    uint32_t a;
    asm("{ .reg .u64 t; cvta.to.shared.u64 t, %1; cvt.u32.u64 %0, t; }" : "=r"(a) : "l"(p));
    return a;
}

__device__ __forceinline__ void ldm_x4(uint32_t* r, uint32_t addr) {
    asm volatile("ldmatrix.sync.aligned.m8n8.x4.shared.b16 {%0,%1,%2,%3}, [%4];"
                 : "=r"(r[0]), "=r"(r[1]), "=r"(r[2]), "=r"(r[3]) : "r"(addr));
}

__device__ __forceinline__ void mma_bf16(float* d, const uint32_t* a, uint32_t b0, uint32_t b1) {
    asm volatile(
        "mma.sync.aligned.m16n8k16.row.col.f32.bf16.bf16.f32 "
        "{%0,%1,%2,%3}, {%4,%5,%6,%7}, {%8,%9}, {%0,%1,%2,%3};"
        : "+f"(d[0]), "+f"(d[1]), "+f"(d[2]), "+f"(d[3])
        : "r"(a[0]), "r"(a[1]), "r"(a[2]), "r"(a[3]), "r"(b0), "r"(b1));
}

__device__ __forceinline__ void load_tile_bf16(
    const __nv_bfloat16* __restrict__ hi, const __nv_bfloat16* __restrict__ lo,
    int stride, int row0, int kbase, int kmax, char* smHi, char* smLo, int tid)
{
    #pragma unroll
    for (int i = 0; i < 8; i++) {
        int idx = i * 256 + tid;
        int r = idx >> 4, c4 = idx & 15;
        int kg = kbase + c4 * 4;
        uint2 vh = make_uint2(0u, 0u), vl = make_uint2(0u, 0u);
        if (kg < kmax) {
            size_t off = (size_t)(row0 + r) * stride + kg;
            vh = *(const uint2*)(hi + off);
            vl = *(const uint2*)(lo + off);
        }
        uint32_t so = (uint32_t)(r * TPAD + c4 * 4) * 2;
        *(uint2*)(smHi + so) = vh;
        *(uint2*)(smLo + so) = vl;
    }
}

__global__ __launch_bounds__(256) void gemm_mma(
    const uint2* Ahi0u, const uint2* Alo0u, int K0,
    const uint2* Ahi1u, const uint2* Alo1u, int K1,
    const uint2* Whiu, const uint2* Wlou,
    const float* __restrict__ bias, float* __restrict__ C, int reverse)
{
    extern __shared__ char sm[];
    const __nv_bfloat16* Ahi0 = (const __nv_bfloat16*)Ahi0u;
    const __nv_bfloat16* Alo0 = (const __nv_bfloat16*)Alo0u;
    const __nv_bfloat16* Ahi1 = (const __nv_bfloat16*)Ahi1u;
    const __nv_bfloat16* Alo1 = (const __nv_bfloat16*)Alo1u;
    const __nv_bfloat16* Whi  = (const __nv_bfloat16*)Whiu;
    const __nv_bfloat16* Wlo  = (const __nv_bfloat16*)Wlou;

    const int tid  = threadIdx.x;
    const int warp = tid >> 5, lane = tid & 31;
    const int tb = blockIdx.x;
    const int n0 = blockIdx.y * 128;
    const int Ktot = K0 + K1;
    const int nkt = (Ktot + BKT - 1) / BKT;

    const int m0w = (warp >> 1) * 32;
    const int n0w = (warp & 1) * 64;
    const int laneRow  = lane & 15;
    const int laneHalf = lane >> 4;

    float* biass = (float*)sm;
    if (tid < 128) biass[tid] = bias[n0 + tid];

    const int arow0 = (reverse ? (T_STEPS - 1 - tb) : tb) * BATCH;
    const int crow0 = tb * BATCH;

    const uint32_t sbAHI = smem_u32(sm + SMG_AHI);
    const uint32_t sbALO = smem_u32(sm + SMG_ALO);
    const uint32_t sbBHI = smem_u32(sm + SMG_BHI);
    const uint32_t sbBLO = smem_u32(sm + SMG_BLO);

    float acc[2][8][4];
    #pragma unroll
    for (int mi = 0; mi < 2; mi++)
        #pragma unroll
        for (int nf = 0; nf < 8; nf++)
            #pragma unroll
            for (int q = 0; q < 4; q++) acc[mi][nf][q] = 0.f;

    for (int kt = 0; kt < nkt; kt++) {
        const int k0 = kt * BKT;
        __syncthreads();
        if (k0 < K0)
            load_tile_bf16(Ahi0, Alo0, K0, arow0, k0, K0, sm + SMG_AHI, sm + SMG_ALO, tid);
        else
            load_tile_bf16(Ahi1, Alo1, K1, arow0, k0 - K0, K1, sm + SMG_AHI, sm + SMG_ALO, tid);
        load_tile_bf16(Whi, Wlo, Ktot, n0, k0, Ktot, sm + SMG_BHI, sm + SMG_BLO, tid);
        __syncthreads();

        #pragma unroll
        for (int ks = 0; ks < 4; ks++) {
            const uint32_t colb = (uint32_t)(ks * 16 + laneHalf * 8) * 2;

            uint32_t ah[2][4], al[2][4];
            #pragma unroll
            for (int mi = 0; mi < 2; mi++) {
                uint32_t ro = (uint32_t)(m0w + mi * 16 + laneRow) * (TPAD * 2) + colb;
                ldm_x4(ah[mi], sbAHI + ro);
                ldm_x4(al[mi], sbALO + ro);
            }
            uint32_t bh[8][2], bl[8][2];
            #pragma unroll
            for (int ni = 0; ni < 4; ni++) {
                uint32_t ro = (uint32_t)(n0w + ni * 16 + laneRow) * (TPAD * 2) + colb;
                uint32_t rb[4];
                ldm_x4(rb, sbBHI + ro);
                bh[2 * ni][0] = rb[0]; bh[2 * ni][1] = rb[2];
                bh[2 * ni + 1][0] = rb[1]; bh[2 * ni + 1][1] = rb[3];
                ldm_x4(rb, sbBLO + ro);
                bl[2 * ni][0] = rb[0]; bl[2 * ni][1] = rb[2];
                bl[2 * ni + 1][0] = rb[1]; bl[2 * ni + 1][1] = rb[3];
            }
            // pass-major ordering for ILP across 16 independent accumulators
            #pragma unroll
            for (int mi = 0; mi < 2; mi++)
                #pragma unroll
                for (int nf = 0; nf < 8; nf++)
                    mma_bf16(acc[mi][nf], ah[mi], bh[nf][0], bh[nf][1]);
            #pragma unroll
            for (int mi = 0; mi < 2; mi++)
                #pragma unroll
                for (int nf = 0; nf < 8; nf++)
                    mma_bf16(acc[mi][nf], ah[mi], bl[nf][0], bl[nf][1]);
            #pragma unroll
            for (int mi = 0; mi < 2; mi++)
                #pragma unroll
                for (int nf = 0; nf < 8; nf++)
                    mma_bf16(acc[mi][nf], al[mi], bh[nf][0], bh[nf][1]);
        }
    }

    // Epilogue: frags -> smem stage (pad 132) -> coalesced global stores with bias
    __syncthreads();
    float* stage = (float*)(sm + 1024);
    {
        const int g = lane >> 2, t4 = lane & 3;
        #pragma unroll
        for (int mi = 0; mi < 2; mi++)
            #pragma unroll
            for (int nf = 0; nf < 8; nf++) {
                int col = n0w + nf * 8 + 2 * t4;
                float* p0 = &stage[(m0w + mi * 16 + g) * 132 + col];
                float* p1 = &stage[(m0w + mi * 16 + g + 8) * 132 + col];
                p0[0] = acc[mi][nf][0]; p0[1] = acc[mi][nf][1];
                p1[0] = acc[mi][nf][2]; p1[1] = acc[mi][nf][3];
            }
    }
    __syncthreads();
    {
        const int col = tid & 127;
        const float bcol = biass[col];
        #pragma unroll 4
        for (int it = 0; it < 64; it++) {
            int r = it * 2 + (tid >> 7);
            C[(size_t)(crow0 + r) * G3E + n0 + col] = stage[r * 132 + col] + bcol;
        }
    }
}

// =================================================================================
__device__ __forceinline__ float sigmf(float x) {
    return 1.0f / (1.0f + __expf(-x));
}

// ---------------------------------------------------------------------------------
// Encoder bidirectional GRU scan (unchanged — passing).
// ---------------------------------------------------------------------------------
__global__ __launch_bounds__(384, 1) void enc_scan(
    const float* __restrict__ Whh_f, const float* __restrict__ bhh_f,
    const float* __restrict__ Whh_b, const float* __restrict__ bhh_b,
    const float* __restrict__ enc_init)
{
    const int j = threadIdx.x;
    const int dir = blockIdx.x >> 7;
    const int b = blockIdx.x & 127;
    const float* Whh = dir ? Whh_b : Whh_f;
    const float* bhh = dir ? bhh_b : bhh_f;
    const float* xp = dir ? g_xpb : g_xpf;

    float w[128];
    #pragma unroll
    for (int k = 0; k < 128; k++) w[k] = Whh[j * 128 + k];
    const float bh = bhh[j];

    __shared__ __align__(16) float h_s[128];
    __shared__ float hh_s[384];
    if (j < 128) h_s[j] = enc_init[dir * 128 + j];
    __syncthreads();

    for (int t = 0; t < T_STEPS; t++) {
        const float* xr = xp + ((size_t)t * BATCH + b) * G3E;
        float pr = 0.f, pz = 0.f, pn = 0.f;
        if (j < 128) { pr = xr[j]; pz = xr[128 + j]; pn = xr[256 + j]; }

        float a0 = 0.f, a1 = 0.f, a2 = 0.f, a3 = 0.f;
        const float4* h4 = (const float4*)h_s;
        #pragma unroll
        for (int kk = 0; kk < 32; kk++) {
            float4 hv = h4[kk];
            a0 += w[4 * kk + 0] * hv.x;
            a1 += w[4 * kk + 1] * hv.y;
            a2 += w[4 * kk + 2] * hv.z;
            a3 += w[4 * kk + 3] * hv.w;
        }
        hh_s[j] = bh + ((a0 + a1) + (a2 + a3));
        __syncthreads();

        if (j < 128) {
            float r = sigmf(pr + hh_s[j]);
            float z = sigmf(pz + hh_s[128 + j]);
            float n = tanhf(pn + r * hh_s[256 + j]);
            float h = (1.f - z) * n + z * h_s[j];
            h_s[j] = h;
            float gc = fminf(fmaxf(h, -CLIPV), CLIPV);
            int tt = dir ? (T_STEPS - 1 - t) : t;
            g_g[((size_t)tt * BATCH + b) * (2 * EDIM) + dir * EDIM + j] = gc;
        }
        __syncthreads();
    }
}

// ---------------------------------------------------------------------------------
// Controller GRU + latent sample + spike/calcium generator (unchanged — passing).
// ---------------------------------------------------------------------------------
#define CTRL_SMEM_FLOATS 40832
#define CTRL_SMEM_BYTES  (CTRL_SMEM_FLOATS * 4)

__global__ __launch_bounds__(384, 1) void ctrl_scan(
    const float* __restrict__ factors, const float* __restrict__ eps,
    const float* __restrict__ Whh, const float* __restrict__ bhh,
    const float* __restrict__ cinit,
    const float* __restrict__ W_mu, const float* __restrict__ b_mu,
    const float* __restrict__ W_lv, const float* __restrict__ b_lv,
    const float* __restrict__ W_spk, const float* __restrict__ b_spk,
    const float* __restrict__ gain_p, const float* __restrict__ biasp_p,
    const float* __restrict__ logtau_p,
    float* __restrict__ out)
{
    extern __shared__ __align__(16) float smf[];
    float* wml  = smf;
    float* wspk = smf + 16896;
    float* h_s  = smf + 39696;
    float* hh_s = smf + 39824;
    float* mlv  = smf + 40208;
    float* gen  = smf + 40336;
    float* bml  = smf + 40404;
    float* bsp  = smf + 40532;

    const int j = threadIdx.x;
    const int b = blockIdx.x;

    float w[128];
    #pragma unroll
    for (int k = 0; k < 128; k++) w[k] = Whh[j * 128 + k];
    const float bh = bhh[j];

    for (int idx = j; idx < 128 * 128; idx += 384) {
        int r = idx >> 7, k = idx & 127;
        wml[r * 132 + k] = (r < 64) ? W_mu[r * 128 + k] : W_lv[(r - 64) * 128 + k];
    }
    for (int idx = j; idx < 300 * 68; idx += 384) {
        int r = idx / 68, k = idx - r * 68;
        wspk[r * 76 + k] = W_spk[idx];
    }
    if (j < 128) { bml[j] = (j < 64) ? b_mu[j] : b_lv[j - 64]; h_s[j] = cinit[j]; }
    if (j < 300) bsp[j] = b_spk[j];

    const float gain  = gain_p[0];
    const float biasp = biasp_p[0];
    const float decay = 1.f - expf(-logtau_p[0]);
    float cal = 0.f;
    __syncthreads();

    const float4* h4 = (const float4*)h_s;

    for (int t = 0; t < T_STEPS; t++) {
        size_t row = (size_t)t * BATCH + b;
        const float* cpr = g_cp + row * G3E;
        float pr = 0.f, pz = 0.f, pn = 0.f, ev = 0.f, fv = 0.f;
        if (j < 128) { pr = cpr[j]; pz = cpr[128 + j]; pn = cpr[256 + j]; }
        if (j < UDIM) ev = eps[row * UDIM + j];
        else if (j < UDIM + FDIM) fv = factors[row * FDIM + (j - UDIM)];

        float a0 = 0.f, a1 = 0.f, a2 = 0.f, a3 = 0.f;
        #pragma unroll
        for (int kk = 0; kk < 32; kk++) {
            float4 hv = h4[kk];
            a0 += w[4 * kk + 0] * hv.x;
            a1 += w[4 * kk + 1] * hv.y;
            a2 += w[4 * kk + 2] * hv.z;
            a3 += w[4 * kk + 3] * hv.w;
        }
        hh_s[j] = bh + ((a0 + a1) + (a2 + a3));
        __syncthreads();

        if (j < 128) {
            float r = sigmf(pr + hh_s[j]);
            float z = sigmf(pz + hh_s[128 + j]);
            float n = tanhf(pn + r * hh_s[256 + j]);
            float h = (1.f - z) * n + z * h_s[j];
            h = fminf(fmaxf(h, -CLIPV), CLIPV);
            h_s[j] = h;
        }
        __syncthreads();

        if (j < 128) {
            float m0 = 0.f, m1 = 0.f, m2 = 0.f, m3 = 0.f;
            const float4* wr = (const float4*)&wml[j * 132];
            #pragma unroll
            for (int kk = 0; kk < 32; kk++) {
                float4 wv = wr[kk];
                float4 hv = h4[kk];
                m0 += wv.x * hv.x; m1 += wv.y * hv.y;
                m2 += wv.z * hv.z; m3 += wv.w * hv.w;
            }
            mlv[j] = bml[j] + ((m0 + m1) + (m2 + m3));
        }
        __syncthreads();

        if (j < UDIM) gen[j] = mlv[j] + __expf(0.5f * mlv[UDIM + j]) * ev;
        else if (j < UDIM + FDIM) gen[j] = fv;
        __syncthreads();

        if (j < NIN) {
            float s0 = 0.f, s1 = 0.f, s2 = 0.f, s3 = 0.f;
            const float4* wr = (const float4*)&wspk[j * 76];
            const float4* g4 = (const float4*)gen;
            #pragma unroll
            for (int kk = 0; kk < 17; kk++) {
                float4 wv = wr[kk];
                float4 gv = g4[kk];
                s0 += wv.x * gv.x; s1 += wv.y * gv.y;
                s2 += wv.z * gv.z; s3 += wv.w * gv.w;
            }
            float logit = bsp[j] + ((s0 + s1) + (s2 + s3));
            float spike = fmaxf(__expf(logit) - 1.f, 0.f);
            cal = cal * decay + gain * spike + biasp;
            out[row * NIN + j] = cal;
        }
    }
}

// ---------------------------------------------------------------------------------
extern "C" void kernel_launch(void* const* d_in, const int* in_sizes, int n_in,
                              void* d_out, int out_size)
{
    (void)in_sizes; (void)n_in; (void)out_size;
    const float* x       = (const float*)d_in[0];
    const float* factors = (const float*)d_in[1];
    const float* eps     = (const float*)d_in[2];
    const float* eWihf   = (const float*)d_in[3];
    const float* eWhhf   = (const float*)d_in[4];
    const float* ebihf   = (const float*)d_in[5];
    const float* ebhhf   = (const float*)d_in[6];
    const float* eWihb   = (const float*)d_in[7];
    const float* eWhhb   = (const float*)d_in[8];
    const float* ebihb   = (const float*)d_in[9];
    const float* ebhhb   = (const float*)d_in[10];
    const float* einit   = (const float*)d_in[11];
    const float* cWih    = (const float*)d_in[12];
    const float* cWhh    = (const float*)d_in[13];
    const float* cbih    = (const float*)d_in[14];
    const float* cbhh    = (const float*)d_in[15];
    const float* cinit   = (const float*)d_in[16];
    const float* Wmu     = (const float*)d_in[17];
    const float* bmu     = (const float*)d_in[18];
    const float* Wlv     = (const float*)d_in[19];
    const float* blv     = (const float*)d_in[20];
    const float* Wspk    = (const float*)d_in[21];
    const float* bspk    = (const float*)d_in[22];
    const float* gain    = (const float*)d_in[23];
    const float* bp      = (const float*)d_in[24];
    const float* ltau    = (const float*)d_in[25];
    float* out = (float*)d_out;

    float *xpf, *xpb, *gg, *cp;
    cudaGetSymbolAddress((void**)&xpf, g_xpf);
    cudaGetSymbolAddress((void**)&xpb, g_xpb);
    cudaGetSymbolAddress((void**)&gg,  g_g);
    cudaGetSymbolAddress((void**)&cp,  g_cp);

    uint2 *xhi, *xlo, *ghi, *glo, *wfhi, *wflo, *wbhi, *wblo, *wchi, *wclo;
    cudaGetSymbolAddress((void**)&xhi, g_xhi);   cudaGetSymbolAddress((void**)&xlo, g_xlo);
    cudaGetSymbolAddress((void**)&ghi, g_ghi);   cudaGetSymbolAddress((void**)&glo, g_glo);
    cudaGetSymbolAddress((void**)&wfhi, g_wfhi); cudaGetSymbolAddress((void**)&wflo, g_wflo);
    cudaGetSymbolAddress((void**)&wbhi, g_wbhi); cudaGetSymbolAddress((void**)&wblo, g_wblo);
    cudaGetSymbolAddress((void**)&wchi, g_wchi); cudaGetSymbolAddress((void**)&wclo, g_wclo);

    cudaFuncSetAttribute(gemm_mma, cudaFuncAttributeMaxDynamicSharedMemorySize, GEMM_SMEM);
    cudaFuncSetAttribute(ctrl_scan, cudaFuncAttributeMaxDynamicSharedMemorySize, CTRL_SMEM_BYTES);

    // ---- pre-convert fp32 -> bf16 hi/lo (x and the three input-proj weights) ----
    conv_split<<<(XN4 + 255) / 256, 256>>>((const float4*)x, xhi, xlo, XN4);
    conv_split<<<(WFN4 + 255) / 256, 256>>>((const float4*)eWihf, wfhi, wflo, WFN4);
    conv_split<<<(WFN4 + 255) / 256, 256>>>((const float4*)eWihb, wbhi, wblo, WFN4);
    conv_split<<<(WCN4 + 255) / 256, 256>>>((const float4*)cWih, wchi, wclo, WCN4);

    dim3 gemm_grid(T_STEPS, G3E / 128);

    // xp_f = x @ enc_Wih_f^T + b ; xp_b = x[::-1] @ enc_Wih_b^T + b
    gemm_mma<<<gemm_grid, 256, GEMM_SMEM>>>(xhi, xlo, NIN, nullptr, nullptr, 0,
                                            wfhi, wflo, ebihf, xpf, 0);
    gemm_mma<<<gemm_grid, 256, GEMM_SMEM>>>(xhi, xlo, NIN, nullptr, nullptr, 0,
                                            wbhi, wblo, ebihb, xpb, 1);

    // bidirectional encoder scan -> g (clipped, original timeline)
    enc_scan<<<256, 384>>>(eWhhf, ebhhf, eWhhb, ebhhb, einit);

    // convert g, then cp = [g, x] @ ctrl_Wih^T + b (K0=256 divisible by 64)
    conv_split<<<(GN4 + 255) / 256, 256>>>((const float4*)gg, ghi, glo, GN4);
    gemm_mma<<<gemm_grid, 256, GEMM_SMEM>>>(ghi, glo, 2 * EDIM, xhi, xlo, NIN,
                                            wchi, wclo, cbih, cp, 0);

    // controller scan -> calcium (d_out)
    ctrl_scan<<<128, 384, CTRL_SMEM_BYTES>>>(factors, eps, cWhh, cbhh, cinit,
                                             Wmu, bmu, Wlv, blv, Wspk, bspk,
                                             gain, bp, ltau, out);
}

// round 6
// speedup vs baseline: 1.4582x; 1.0422x over previous
#include <cuda_runtime.h>
#include <cuda_bf16.h>
#include <cstdint>
#include <cstddef>

#define T_STEPS 500
#define BATCH   128
#define NIN     300
#define EDIM    128
#define CDIM    128
#define UDIM    64
#define FDIM    4
#define G3E     384      // 3*E == 3*C
#define CLIPV   5.0f

// ---------------- scratch (device globals; no runtime allocation) ----------------
__device__ float g_xpf[(size_t)T_STEPS * BATCH * G3E];
__device__ float g_xpb[(size_t)T_STEPS * BATCH * G3E];
__device__ float g_g  [(size_t)T_STEPS * BATCH * 2 * EDIM];
__device__ float g_cp [(size_t)T_STEPS * BATCH * G3E];

// bf16 hi/lo pre-converted operands (uint2-typed for guaranteed 8B alignment)
#define XN4   (T_STEPS * BATCH * NIN / 4)
#define GN4   (T_STEPS * BATCH * 2 * EDIM / 4)
#define WFN4  (G3E * NIN / 4)
#define WCN4  (G3E * (2 * EDIM + NIN) / 4)
__device__ uint2 g_xhi[XN4],  g_xlo[XN4];
__device__ uint2 g_ghi[GN4],  g_glo[GN4];
__device__ uint2 g_wfhi[WFN4], g_wflo[WFN4];
__device__ uint2 g_wbhi[WFN4], g_wblo[WFN4];
__device__ uint2 g_wchi[WCN4], g_wclo[WCN4];

// ---------------- packed f32x2 helpers (Blackwell family-wide, non-'a') ----------
#define FMA2(acc, a, b) \
    asm volatile("fma.rn.f32x2 %0, %1, %2, %0;" : "+l"(acc) : "l"(a), "l"(b))

__device__ __forceinline__ float sum2(unsigned long long v) {
    float lo, hi;
    asm("mov.b64 {%0, %1}, %2;" : "=f"(lo), "=f"(hi) : "l"(v));
    return lo + hi;
}

// =================================================================================
// fp32 -> bf16 (hi, lo) split conversion, vectorized x4
// =================================================================================
__device__ __forceinline__ uint32_t pack2(__nv_bfloat16 a, __nv_bfloat16 b) {
    return ((uint32_t)__bfloat16_as_ushort(b) << 16) | __bfloat16_as_ushort(a);
}

__global__ __launch_bounds__(256) void conv_split(
    const float4* __restrict__ src, uint2* __restrict__ hi, uint2* __restrict__ lo, int n4)
{
    int i = blockIdx.x * 256 + threadIdx.x;
    if (i >= n4) return;
    float4 v = src[i];
    __nv_bfloat16 h0 = __float2bfloat16_rn(v.x);
    __nv_bfloat16 h1 = __float2bfloat16_rn(v.y);
    __nv_bfloat16 h2 = __float2bfloat16_rn(v.z);
    __nv_bfloat16 h3 = __float2bfloat16_rn(v.w);
    hi[i] = make_uint2(pack2(h0, h1), pack2(h2, h3));
    __nv_bfloat16 l0 = __float2bfloat16_rn(v.x - __bfloat162float(h0));
    __nv_bfloat16 l1 = __float2bfloat16_rn(v.y - __bfloat162float(h1));
    __nv_bfloat16 l2 = __float2bfloat16_rn(v.z - __bfloat162float(h2));
    __nv_bfloat16 l3 = __float2bfloat16_rn(v.w - __bfloat162float(h3));
    lo[i] = make_uint2(pack2(l0, l1), pack2(l2, l3));
}

// =================================================================================
// Tensor-core GEMM via portable warp mma (bf16 split-2, 3 passes, fp32 accum)
//   2-stage cp.async pipeline. CTA tile 128x128, BK=64, 8 warps (4m x 2n).
// =================================================================================
#define BKT 64
#define TPAD 72
#define TILE_B (128 * TPAD * 2)       // 18432 bytes per operand tile
#define STAGE_B (4 * TILE_B)          // AHI/ALO/BHI/BLO = 73728 per stage
#define SMG_BASE 1024
#define GEMM_SMEM (SMG_BASE + 2 * STAGE_B)   // 148480

__device__ __forceinline__ uint32_t smem_u32(const void* p) {
    uint32_t a;
    asm("{ .reg .u64 t; cvta.to.shared.u64 t, %1; cvt.u32.u64 %0, t; }" : "=r"(a) : "l"(p));
    return a;
}

__device__ __forceinline__ void ldm_x4(uint32_t* r, uint32_t addr) {
    asm volatile("ldmatrix.sync.aligned.m8n8.x4.shared.b16 {%0,%1,%2,%3}, [%4];"
                 : "=r"(r[0]), "=r"(r[1]), "=r"(r[2]), "=r"(r[3]) : "r"(addr));
}

__device__ __forceinline__ void mma_bf16(float* d, const uint32_t* a, uint32_t b0, uint32_t b1) {
    asm volatile(
        "mma.sync.aligned.m16n8k16.row.col.f32.bf16.bf16.f32 "
        "{%0,%1,%2,%3}, {%4,%5,%6,%7}, {%8,%9}, {%0,%1,%2,%3};"
        : "+f"(d[0]), "+f"(d[1]), "+f"(d[2]), "+f"(d[3])
        : "r"(a[0]), "r"(a[1]), "r"(a[2]), "r"(a[3]), "r"(b0), "r"(b1));
}

// async copy of one 128x64 hi/lo tile pair into smem (8B transactions, zfill OOB)
__device__ __forceinline__ void cp_tile_pair(
    const __nv_bfloat16* __restrict__ hi, const __nv_bfloat16* __restrict__ lo,
    int stride, int row0, int kbase, int kmax, uint32_t smHi, uint32_t smLo, int tid)
{
    #pragma unroll
    for (int i = 0; i < 8; i++) {
        int idx = i * 256 + tid;
        int r = idx >> 4, c4 = idx & 15;
        int kg = kbase + c4 * 4;
        int sz = (kg < kmax) ? 8 : 0;
        int kgc = (kg < kmax) ? kg : 0;                 // keep src in-bounds
        size_t off = (size_t)(row0 + r) * stride + kgc;
        uint32_t so = (uint32_t)(r * TPAD + c4 * 4) * 2;
        asm volatile("cp.async.ca.shared.global [%0], [%1], 8, %2;"
                     :: "r"(smHi + so), "l"(hi + off), "r"(sz));
        asm volatile("cp.async.ca.shared.global [%0], [%1], 8, %2;"
                     :: "r"(smLo + so), "l"(lo + off), "r"(sz));
    }
}

__global__ __launch_bounds__(256) void gemm_mma(
    const uint2* Ahi0u, const uint2* Alo0u, int K0,
    const uint2* Ahi1u, const uint2* Alo1u, int K1,
    const uint2* Whiu, const uint2* Wlou,
    const float* __restrict__ bias, float* __restrict__ C, int reverse)
{
    extern __shared__ char sm[];
    const __nv_bfloat16* Ahi0 = (const __nv_bfloat16*)Ahi0u;
    const __nv_bfloat16* Alo0 = (const __nv_bfloat16*)Alo0u;
    const __nv_bfloat16* Ahi1 = (const __nv_bfloat16*)Ahi1u;
    const __nv_bfloat16* Alo1 = (const __nv_bfloat16*)Alo1u;
    const __nv_bfloat16* Whi  = (const __nv_bfloat16*)Whiu;
    const __nv_bfloat16* Wlo  = (const __nv_bfloat16*)Wlou;

    const int tid  = threadIdx.x;
    const int warp = tid >> 5, lane = tid & 31;
    const int tb = blockIdx.x;
    const int n0 = blockIdx.y * 128;
    const int Ktot = K0 + K1;
    const int nkt = (Ktot + BKT - 1) / BKT;

    const int m0w = (warp >> 1) * 32;
    const int n0w = (warp & 1) * 64;
    const int laneRow  = lane & 15;
    const int laneHalf = lane >> 4;

    float* biass = (float*)sm;
    if (tid < 128) biass[tid] = bias[n0 + tid];

    const int arow0 = (reverse ? (T_STEPS - 1 - tb) : tb) * BATCH;
    const int crow0 = tb * BATCH;

    const uint32_t smBase = smem_u32(sm + SMG_BASE);

    float acc[2][8][4];
    #pragma unroll
    for (int mi = 0; mi < 2; mi++)
        #pragma unroll
        for (int nf = 0; nf < 8; nf++)
            #pragma unroll
            for (int q = 0; q < 4; q++) acc[mi][nf][q] = 0.f;

    // issue loads for K-tile kt into stage (kt & 1)
    auto issue_tile = [&](int kt) {
        const int k0 = kt * BKT;
        const uint32_t stg = smBase + (uint32_t)(kt & 1) * STAGE_B;
        if (k0 < K0)
            cp_tile_pair(Ahi0, Alo0, K0, arow0, k0, K0, stg, stg + TILE_B, tid);
        else
            cp_tile_pair(Ahi1, Alo1, K1, arow0, k0 - K0, K1, stg, stg + TILE_B, tid);
        cp_tile_pair(Whi, Wlo, Ktot, n0, k0, Ktot, stg + 2 * TILE_B, stg + 3 * TILE_B, tid);
    };

    issue_tile(0);
    asm volatile("cp.async.commit_group;" ::: "memory");

    for (int kt = 0; kt < nkt; kt++) {
        if (kt + 1 < nkt) issue_tile(kt + 1);
        asm volatile("cp.async.commit_group;" ::: "memory");
        asm volatile("cp.async.wait_group 1;" ::: "memory");
        __syncthreads();

        const uint32_t stg = smBase + (uint32_t)(kt & 1) * STAGE_B;
        const uint32_t sbAHI = stg;
        const uint32_t sbALO = stg + TILE_B;
        const uint32_t sbBHI = stg + 2 * TILE_B;
        const uint32_t sbBLO = stg + 3 * TILE_B;

        #pragma unroll
        for (int ks = 0; ks < 4; ks++) {
            const uint32_t colb = (uint32_t)(ks * 16 + laneHalf * 8) * 2;

            uint32_t ah[2][4], al[2][4];
            #pragma unroll
            for (int mi = 0; mi < 2; mi++) {
                uint32_t ro = (uint32_t)(m0w + mi * 16 + laneRow) * (TPAD * 2) + colb;
                ldm_x4(ah[mi], sbAHI + ro);
                ldm_x4(al[mi], sbALO + ro);
            }
            uint32_t bh[8][2], bl[8][2];
            #pragma unroll
            for (int ni = 0; ni < 4; ni++) {
                uint32_t ro = (uint32_t)(n0w + ni * 16 + laneRow) * (TPAD * 2) + colb;
                uint32_t rb[4];
                ldm_x4(rb, sbBHI + ro);
                bh[2 * ni][0] = rb[0]; bh[2 * ni][1] = rb[2];
                bh[2 * ni + 1][0] = rb[1]; bh[2 * ni + 1][1] = rb[3];
                ldm_x4(rb, sbBLO + ro);
                bl[2 * ni][0] = rb[0]; bl[2 * ni][1] = rb[2];
                bl[2 * ni + 1][0] = rb[1]; bl[2 * ni + 1][1] = rb[3];
            }
            #pragma unroll
            for (int mi = 0; mi < 2; mi++)
                #pragma unroll
                for (int nf = 0; nf < 8; nf++)
                    mma_bf16(acc[mi][nf], ah[mi], bh[nf][0], bh[nf][1]);
            #pragma unroll
            for (int mi = 0; mi < 2; mi++)
                #pragma unroll
                for (int nf = 0; nf < 8; nf++)
                    mma_bf16(acc[mi][nf], ah[mi], bl[nf][0], bl[nf][1]);
            #pragma unroll
            for (int mi = 0; mi < 2; mi++)
                #pragma unroll
                for (int nf = 0; nf < 8; nf++)
                    mma_bf16(acc[mi][nf], al[mi], bh[nf][0], bh[nf][1]);
        }
        __syncthreads();
    }

    // Epilogue: frags -> smem stage (pad 132) -> coalesced global stores with bias
    float* stage = (float*)(sm + SMG_BASE);
    {
        const int g = lane >> 2, t4 = lane & 3;
        #pragma unroll
        for (int mi = 0; mi < 2; mi++)
            #pragma unroll
            for (int nf = 0; nf < 8; nf++) {
                int col = n0w + nf * 8 + 2 * t4;
                float* p0 = &stage[(m0w + mi * 16 + g) * 132 + col];
                float* p1 = &stage[(m0w + mi * 16 + g + 8) * 132 + col];
                p0[0] = acc[mi][nf][0]; p0[1] = acc[mi][nf][1];
                p1[0] = acc[mi][nf][2]; p1[1] = acc[mi][nf][3];
            }
    }
    __syncthreads();
    {
        const int col = tid & 127;
        const float bcol = biass[col];
        #pragma unroll 4
        for (int it = 0; it < 64; it++) {
            int r = it * 2 + (tid >> 7);
            C[(size_t)(crow0 + r) * G3E + n0 + col] = stage[r * 132 + col] + bcol;
        }
    }
}

// =================================================================================
__device__ __forceinline__ float sigmf(float x) {
    return 1.0f / (1.0f + __expf(-x));
}

// ---------------------------------------------------------------------------------
// Encoder bidirectional GRU scan — f32x2-packed hh dot.
// ---------------------------------------------------------------------------------
__global__ __launch_bounds__(384, 1) void enc_scan(
    const float* __restrict__ Whh_f, const float* __restrict__ bhh_f,
    const float* __restrict__ Whh_b, const float* __restrict__ bhh_b,
    const float* __restrict__ enc_init)
{
    const int j = threadIdx.x;
    const int dir = blockIdx.x >> 7;
    const int b = blockIdx.x & 127;
    const float* Whh = dir ? Whh_b : Whh_f;
    const float* bhh = dir ? bhh_b : bhh_f;
    const float* xp = dir ? g_xpb : g_xpf;

    unsigned long long w2[64];
    {
        const unsigned long long* wr = (const unsigned long long*)(Whh + j * 128);
        #pragma unroll
        for (int k = 0; k < 64; k++) w2[k] = wr[k];
    }
    const float bh = bhh[j];

    __shared__ __align__(16) float h_s[128];
    __shared__ float hh_s[384];
    if (j < 128) h_s[j] = enc_init[dir * 128 + j];
    __syncthreads();

    const ulonglong2* h2v = (const ulonglong2*)h_s;

    for (int t = 0; t < T_STEPS; t++) {
        const float* xr = xp + ((size_t)t * BATCH + b) * G3E;
        float pr = 0.f, pz = 0.f, pn = 0.f;
        if (j < 128) { pr = xr[j]; pz = xr[128 + j]; pn = xr[256 + j]; }

        unsigned long long a01 = 0ull, a23 = 0ull;
        #pragma unroll
        for (int kk = 0; kk < 32; kk++) {
            ulonglong2 hv = h2v[kk];
            FMA2(a01, w2[2 * kk + 0], hv.x);
            FMA2(a23, w2[2 * kk + 1], hv.y);
        }
        hh_s[j] = bh + (sum2(a01) + sum2(a23));
        __syncthreads();

        if (j < 128) {
            float r = sigmf(pr + hh_s[j]);
            float z = sigmf(pz + hh_s[128 + j]);
            float n = tanhf(pn + r * hh_s[256 + j]);
            float h = (1.f - z) * n + z * h_s[j];
            h_s[j] = h;
            float gc = fminf(fmaxf(h, -CLIPV), CLIPV);
            int tt = dir ? (T_STEPS - 1 - t) : t;
            g_g[((size_t)tt * BATCH + b) * (2 * EDIM) + dir * EDIM + j] = gc;
        }
        __syncthreads();
    }
}

// ---------------------------------------------------------------------------------
// Controller GRU + latent sample + spike/calcium generator — f32x2-packed dots.
// ---------------------------------------------------------------------------------
#define CTRL_SMEM_FLOATS 40832
#define CTRL_SMEM_BYTES  (CTRL_SMEM_FLOATS * 4)

__global__ __launch_bounds__(384, 1) void ctrl_scan(
    const float* __restrict__ factors, const float* __restrict__ eps,
    const float* __restrict__ Whh, const float* __restrict__ bhh,
    const float* __restrict__ cinit,
    const float* __restrict__ W_mu, const float* __restrict__ b_mu,
    const float* __restrict__ W_lv, const float* __restrict__ b_lv,
    const float* __restrict__ W_spk, const float* __restrict__ b_spk,
    const float* __restrict__ gain_p, const float* __restrict__ biasp_p,
    const float* __restrict__ logtau_p,
    float* __restrict__ out)
{
    extern __shared__ __align__(16) float smf[];
    float* wml  = smf;            // 128 x 132
    float* wspk = smf + 16896;    // 300 x 76
    float* h_s  = smf + 39696;    // 128 (16B aligned: 158784 % 16 == 0)
    float* hh_s = smf + 39824;    // 384
    float* mlv  = smf + 40208;    // 128
    float* gen  = smf + 40336;    // 68 (16B aligned: 161344 % 16 == 0)
    float* bml  = smf + 40404;    // 128
    float* bsp  = smf + 40532;    // 300

    const int j = threadIdx.x;
    const int b = blockIdx.x;

    unsigned long long w2[64];
    {
        const unsigned long long* wr = (const unsigned long long*)(Whh + j * 128);
        #pragma unroll
        for (int k = 0; k < 64; k++) w2[k] = wr[k];
    }
    const float bh = bhh[j];

    for (int idx = j; idx < 128 * 128; idx += 384) {
        int r = idx >> 7, k = idx & 127;
        wml[r * 132 + k] = (r < 64) ? W_mu[r * 128 + k] : W_lv[(r - 64) * 128 + k];
    }
    for (int idx = j; idx < 300 * 68; idx += 384) {
        int r = idx / 68, k = idx - r * 68;
        wspk[r * 76 + k] = W_spk[idx];
    }
    if (j < 128) { bml[j] = (j < 64) ? b_mu[j] : b_lv[j - 64]; h_s[j] = cinit[j]; }
    if (j < 300) bsp[j] = b_spk[j];

    const float gain  = gain_p[0];
    const float biasp = biasp_p[0];
    const float decay = 1.f - expf(-logtau_p[0]);
    float cal = 0.f;
    __syncthreads();

    const ulonglong2* h2v = (const ulonglong2*)h_s;
    const ulonglong2* g2v = (const ulonglong2*)gen;

    for (int t = 0; t < T_STEPS; t++) {
        size_t row = (size_t)t * BATCH + b;
        const float* cpr = g_cp + row * G3E;
        float pr = 0.f, pz = 0.f, pn = 0.f, ev = 0.f, fv = 0.f;
        if (j < 128) { pr = cpr[j]; pz = cpr[128 + j]; pn = cpr[256 + j]; }
        if (j < UDIM) ev = eps[row * UDIM + j];
        else if (j < UDIM + FDIM) fv = factors[row * FDIM + (j - UDIM)];

        // hh = Whh @ h + bhh (packed)
        unsigned long long a01 = 0ull, a23 = 0ull;
        #pragma unroll
        for (int kk = 0; kk < 32; kk++) {
            ulonglong2 hv = h2v[kk];
            FMA2(a01, w2[2 * kk + 0], hv.x);
            FMA2(a23, w2[2 * kk + 1], hv.y);
        }
        hh_s[j] = bh + (sum2(a01) + sum2(a23));
        __syncthreads();

        // gates, clip
        if (j < 128) {
            float r = sigmf(pr + hh_s[j]);
            float z = sigmf(pz + hh_s[128 + j]);
            float n = tanhf(pn + r * hh_s[256 + j]);
            float h = (1.f - z) * n + z * h_s[j];
            h = fminf(fmaxf(h, -CLIPV), CLIPV);
            h_s[j] = h;
        }
        __syncthreads();

        // mu (j<64) / lv (64<=j<128), packed
        if (j < 128) {
            unsigned long long m01 = 0ull, m23 = 0ull;
            const ulonglong2* wr2 = (const ulonglong2*)&wml[j * 132];
            #pragma unroll
            for (int kk = 0; kk < 32; kk++) {
                ulonglong2 wv = wr2[kk];
                ulonglong2 hv = h2v[kk];
                FMA2(m01, wv.x, hv.x);
                FMA2(m23, wv.y, hv.y);
            }
            mlv[j] = bml[j] + (sum2(m01) + sum2(m23));
        }
        __syncthreads();

        // u = mu + exp(0.5 lv) * eps ; gen = [u, f]
        if (j < UDIM) gen[j] = mlv[j] + __expf(0.5f * mlv[UDIM + j]) * ev;
        else if (j < UDIM + FDIM) gen[j] = fv;
        __syncthreads();

        // spike + calcium, packed
        if (j < NIN) {
            unsigned long long s01 = 0ull, s23 = 0ull;
            const ulonglong2* wr2 = (const ulonglong2*)&wspk[j * 76];
            #pragma unroll
            for (int kk = 0; kk < 17; kk++) {
                ulonglong2 wv = wr2[kk];
                ulonglong2 gv = g2v[kk];
                FMA2(s01, wv.x, gv.x);
                FMA2(s23, wv.y, gv.y);
            }
            float logit = bsp[j] + (sum2(s01) + sum2(s23));
            float spike = fmaxf(__expf(logit) - 1.f, 0.f);
            cal = cal * decay + gain * spike + biasp;
            out[row * NIN + j] = cal;
        }
    }
}

// ---------------------------------------------------------------------------------
extern "C" void kernel_launch(void* const* d_in, const int* in_sizes, int n_in,
                              void* d_out, int out_size)
{
    (void)in_sizes; (void)n_in; (void)out_size;
    const float* x       = (const float*)d_in[0];
    const float* factors = (const float*)d_in[1];
    const float* eps     = (const float*)d_in[2];
    const float* eWihf   = (const float*)d_in[3];
    const float* eWhhf   = (const float*)d_in[4];
    const float* ebihf   = (const float*)d_in[5];
    const float* ebhhf   = (const float*)d_in[6];
    const float* eWihb   = (const float*)d_in[7];
    const float* eWhhb   = (const float*)d_in[8];
    const float* ebihb   = (const float*)d_in[9];
    const float* ebhhb   = (const float*)d_in[10];
    const float* einit   = (const float*)d_in[11];
    const float* cWih    = (const float*)d_in[12];
    const float* cWhh    = (const float*)d_in[13];
    const float* cbih    = (const float*)d_in[14];
    const float* cbhh    = (const float*)d_in[15];
    const float* cinit   = (const float*)d_in[16];
    const float* Wmu     = (const float*)d_in[17];
    const float* bmu     = (const float*)d_in[18];
    const float* Wlv     = (const float*)d_in[19];
    const float* blv     = (const float*)d_in[20];
    const float* Wspk    = (const float*)d_in[21];
    const float* bspk    = (const float*)d_in[22];
    const float* gain    = (const float*)d_in[23];
    const float* bp      = (const float*)d_in[24];
    const float* ltau    = (const float*)d_in[25];
    float* out = (float*)d_out;

    float *xpf, *xpb, *gg, *cp;
    cudaGetSymbolAddress((void**)&xpf, g_xpf);
    cudaGetSymbolAddress((void**)&xpb, g_xpb);
    cudaGetSymbolAddress((void**)&gg,  g_g);
    cudaGetSymbolAddress((void**)&cp,  g_cp);

    uint2 *xhi, *xlo, *ghi, *glo, *wfhi, *wflo, *wbhi, *wblo, *wchi, *wclo;
    cudaGetSymbolAddress((void**)&xhi, g_xhi);   cudaGetSymbolAddress((void**)&xlo, g_xlo);
    cudaGetSymbolAddress((void**)&ghi, g_ghi);   cudaGetSymbolAddress((void**)&glo, g_glo);
    cudaGetSymbolAddress((void**)&wfhi, g_wfhi); cudaGetSymbolAddress((void**)&wflo, g_wflo);
    cudaGetSymbolAddress((void**)&wbhi, g_wbhi); cudaGetSymbolAddress((void**)&wblo, g_wblo);
    cudaGetSymbolAddress((void**)&wchi, g_wchi); cudaGetSymbolAddress((void**)&wclo, g_wclo);

    cudaFuncSetAttribute(gemm_mma, cudaFuncAttributeMaxDynamicSharedMemorySize, GEMM_SMEM);
    cudaFuncSetAttribute(ctrl_scan, cudaFuncAttributeMaxDynamicSharedMemorySize, CTRL_SMEM_BYTES);

    // ---- pre-convert fp32 -> bf16 hi/lo (x and the three input-proj weights) ----
    conv_split<<<(XN4 + 255) / 256, 256>>>((const float4*)x, xhi, xlo, XN4);
    conv_split<<<(WFN4 + 255) / 256, 256>>>((const float4*)eWihf, wfhi, wflo, WFN4);
    conv_split<<<(WFN4 + 255) / 256, 256>>>((const float4*)eWihb, wbhi, wblo, WFN4);
    conv_split<<<(WCN4 + 255) / 256, 256>>>((const float4*)cWih, wchi, wclo, WCN4);

    dim3 gemm_grid(T_STEPS, G3E / 128);

    // xp_f = x @ enc_Wih_f^T + b ; xp_b = x[::-1] @ enc_Wih_b^T + b
    gemm_mma<<<gemm_grid, 256, GEMM_SMEM>>>(xhi, xlo, NIN, nullptr, nullptr, 0,
                                            wfhi, wflo, ebihf, xpf, 0);
    gemm_mma<<<gemm_grid, 256, GEMM_SMEM>>>(xhi, xlo, NIN, nullptr, nullptr, 0,
                                            wbhi, wblo, ebihb, xpb, 1);

    // bidirectional encoder scan -> g (clipped, original timeline)
    enc_scan<<<256, 384>>>(eWhhf, ebhhf, eWhhb, ebhhb, einit);

    // convert g, then cp = [g, x] @ ctrl_Wih^T + b (K0=256 divisible by 64)
    conv_split<<<(GN4 + 255) / 256, 256>>>((const float4*)gg, ghi, glo, GN4);
    gemm_mma<<<gemm_grid, 256, GEMM_SMEM>>>(ghi, glo, 2 * EDIM, xhi, xlo, NIN,
                                            wchi, wclo, cbih, cp, 0);

    // controller scan -> calcium (d_out)
    ctrl_scan<<<128, 384, CTRL_SMEM_BYTES>>>(factors, eps, cWhh, cbhh, cinit,
                                             Wmu, bmu, Wlv, blv, Wspk, bspk,
                                             gain, bp, ltau, out);
}

// round 8
// speedup vs baseline: 1.6035x; 1.0997x over previous
#include <cuda_runtime.h>
#include <cuda_fp16.h>
#include <cstdint>
#include <cstddef>

#define T_STEPS 500
#define BATCH   128
#define NIN     300
#define EDIM    128
#define CDIM    128
#define UDIM    64
#define FDIM    4
#define G3E     384      // 3*E == 3*C
#define CLIPV   5.0f

// ---------------- scratch (device globals; no runtime allocation) ----------------
__device__ float g_xpf[(size_t)T_STEPS * BATCH * G3E];
__device__ float g_xpb[(size_t)T_STEPS * BATCH * G3E];
__device__ float g_g  [(size_t)T_STEPS * BATCH * 2 * EDIM];
__device__ float g_cp [(size_t)T_STEPS * BATCH * G3E];

// fp16 pre-converted operands: A operands single precision-slice, W operands hi+lo
#define XN4   (T_STEPS * BATCH * NIN / 4)
#define GN4   (T_STEPS * BATCH * 2 * EDIM / 4)
#define WFN4  (G3E * NIN / 4)
#define WCN4  (G3E * (2 * EDIM + NIN) / 4)
__device__ uint2 g_xh[XN4];
__device__ uint2 g_gh[GN4];
__device__ uint2 g_wfh[WFN4], g_wfl[WFN4];
__device__ uint2 g_wbh[WFN4], g_wbl[WFN4];
__device__ uint2 g_wch[WCN4], g_wcl[WCN4];

// ---------------- packed f32x2 helpers ----------------
#define FMA2(acc, a, b) \
    asm volatile("fma.rn.f32x2 %0, %1, %2, %0;" : "+l"(acc) : "l"(a), "l"(b))

__device__ __forceinline__ float sum2(unsigned long long v) {
    float lo, hi;
    asm("mov.b64 {%0, %1}, %2;" : "=f"(lo), "=f"(hi) : "l"(v));
    return lo + hi;
}

// =================================================================================
// fp32 -> fp16 conversions
// =================================================================================
__device__ __forceinline__ uint32_t packh2(__half a, __half b) {
    return ((uint32_t)__half_as_ushort(b) << 16) | __half_as_ushort(a);
}

__global__ __launch_bounds__(256) void conv_half(
    const float4* __restrict__ src, uint2* __restrict__ dst, int n4)
{
    int i = blockIdx.x * 256 + threadIdx.x;
    if (i >= n4) return;
    float4 v = src[i];
    dst[i] = make_uint2(packh2(__float2half_rn(v.x), __float2half_rn(v.y)),
                        packh2(__float2half_rn(v.z), __float2half_rn(v.w)));
}

__global__ __launch_bounds__(256) void conv_half_split(
    const float4* __restrict__ src, uint2* __restrict__ hi, uint2* __restrict__ lo, int n4)
{
    int i = blockIdx.x * 256 + threadIdx.x;
    if (i >= n4) return;
    float4 v = src[i];
    __half h0 = __float2half_rn(v.x);
    __half h1 = __float2half_rn(v.y);
    __half h2 = __float2half_rn(v.z);
    __half h3 = __float2half_rn(v.w);
    hi[i] = make_uint2(packh2(h0, h1), packh2(h2, h3));
    __half l0 = __float2half_rn(v.x - __half2float(h0));
    __half l1 = __float2half_rn(v.y - __half2float(h1));
    __half l2 = __float2half_rn(v.z - __half2float(h2));
    __half l3 = __float2half_rn(v.w - __half2float(h3));
    lo[i] = make_uint2(packh2(l0, l1), packh2(l2, l3));
}

// =================================================================================
// Tensor-core GEMM: fp16 split-2, TWO passes (Ah*Bh + Ah*Bl), fp32 accum.
//   2-stage cp.async pipeline; CTA tile 128x128, BK=64, 8 warps; 2 CTAs/SM.
// =================================================================================
#define BKT 64
#define TPAD 72
#define TILE_B (128 * TPAD * 2)       // 18432 bytes per operand tile
#define STAGE_B (3 * TILE_B)          // A, BHI, BLO = 55296 per stage
#define SMG_BASE 1024
#define GEMM_SMEM (SMG_BASE + 2 * STAGE_B)   // 111616 -> 2 CTAs/SM

__device__ __forceinline__ uint32_t smem_u32(const void* p) {
    uint32_t a;
    asm("{ .reg .u64 t; cvta.to.shared.u64 t, %1; cvt.u32.u64 %0, t; }" : "=r"(a) : "l"(p));
    return a;
}

__device__ __forceinline__ void ldm_x4(uint32_t* r, uint32_t addr) {
    asm volatile("ldmatrix.sync.aligned.m8n8.x4.shared.b16 {%0,%1,%2,%3}, [%4];"
                 : "=r"(r[0]), "=r"(r[1]), "=r"(r[2]), "=r"(r[3]) : "r"(addr));
}

__device__ __forceinline__ void mma_fp16(float* d, const uint32_t* a, uint32_t b0, uint32_t b1) {
    asm volatile(
        "mma.sync.aligned.m16n8k16.row.col.f32.f16.f16.f32 "
        "{%0,%1,%2,%3}, {%4,%5,%6,%7}, {%8,%9}, {%0,%1,%2,%3};"
        : "+f"(d[0]), "+f"(d[1]), "+f"(d[2]), "+f"(d[3])
        : "r"(a[0]), "r"(a[1]), "r"(a[2]), "r"(a[3]), "r"(b0), "r"(b1));
}

// async copy of one 128x64 fp16 tile into smem (8B transactions, zfill OOB)
__device__ __forceinline__ void cp_tile(
    const __half* __restrict__ src, int stride, int row0,
    int kbase, int kmax, uint32_t smDst, int tid)
{
    #pragma unroll
    for (int i = 0; i < 8; i++) {
        int idx = i * 256 + tid;
        int r = idx >> 4, c4 = idx & 15;
        int kg = kbase + c4 * 4;
        int sz = (kg < kmax) ? 8 : 0;
        int kgc = (kg < kmax) ? kg : 0;
        size_t off = (size_t)(row0 + r) * stride + kgc;
        uint32_t so = (uint32_t)(r * TPAD + c4 * 4) * 2;
        asm volatile("cp.async.ca.shared.global [%0], [%1], 8, %2;"
                     :: "r"(smDst + so), "l"(src + off), "r"(sz));
    }
}

__global__ __launch_bounds__(256, 2) void gemm_mma(
    const uint2* Ah0u, int K0, const uint2* Ah1u, int K1,
    const uint2* Whiu, const uint2* Wlou,
    const float* __restrict__ bias, float* __restrict__ C, int reverse)
{
    extern __shared__ char sm[];
    const __half* Ah0 = (const __half*)Ah0u;
    const __half* Ah1 = (const __half*)Ah1u;
    const __half* Whi = (const __half*)Whiu;
    const __half* Wlo = (const __half*)Wlou;

    const int tid  = threadIdx.x;
    const int warp = tid >> 5, lane = tid & 31;
    const int tb = blockIdx.x;
    const int n0 = blockIdx.y * 128;
    const int Ktot = K0 + K1;
    const int nkt = (Ktot + BKT - 1) / BKT;

    const int m0w = (warp >> 1) * 32;
    const int n0w = (warp & 1) * 64;
    const int laneRow  = lane & 15;
    const int laneHalf = lane >> 4;

    float* biass = (float*)sm;
    if (tid < 128) biass[tid] = bias[n0 + tid];

    const int arow0 = (reverse ? (T_STEPS - 1 - tb) : tb) * BATCH;
    const int crow0 = tb * BATCH;

    const uint32_t smBase = smem_u32(sm + SMG_BASE);

    float acc[2][8][4];
    #pragma unroll
    for (int mi = 0; mi < 2; mi++)
        #pragma unroll
        for (int nf = 0; nf < 8; nf++)
            #pragma unroll
            for (int q = 0; q < 4; q++) acc[mi][nf][q] = 0.f;

    auto issue_tile = [&](int kt) {
        const int k0 = kt * BKT;
        const uint32_t stg = smBase + (uint32_t)(kt & 1) * STAGE_B;
        if (k0 < K0)
            cp_tile(Ah0, K0, arow0, k0, K0, stg, tid);
        else
            cp_tile(Ah1, K1, arow0, k0 - K0, K1, stg, tid);
        cp_tile(Whi, Ktot, n0, k0, Ktot, stg + TILE_B, tid);
        cp_tile(Wlo, Ktot, n0, k0, Ktot, stg + 2 * TILE_B, tid);
    };

    issue_tile(0);
    asm volatile("cp.async.commit_group;" ::: "memory");

    for (int kt = 0; kt < nkt; kt++) {
        if (kt + 1 < nkt) issue_tile(kt + 1);
        asm volatile("cp.async.commit_group;" ::: "memory");
        asm volatile("cp.async.wait_group 1;" ::: "memory");
        __syncthreads();

        const uint32_t stg = smBase + (uint32_t)(kt & 1) * STAGE_B;
        const uint32_t sbA   = stg;
        const uint32_t sbBHI = stg + TILE_B;
        const uint32_t sbBLO = stg + 2 * TILE_B;

        #pragma unroll
        for (int ks = 0; ks < 4; ks++) {
            const uint32_t colb = (uint32_t)(ks * 16 + laneHalf * 8) * 2;

            uint32_t ah[2][4];
            #pragma unroll
            for (int mi = 0; mi < 2; mi++) {
                uint32_t ro = (uint32_t)(m0w + mi * 16 + laneRow) * (TPAD * 2) + colb;
                ldm_x4(ah[mi], sbA + ro);
            }
            uint32_t bh[8][2], bl[8][2];
            #pragma unroll
            for (int ni = 0; ni < 4; ni++) {
                uint32_t ro = (uint32_t)(n0w + ni * 16 + laneRow) * (TPAD * 2) + colb;
                uint32_t rb[4];
                ldm_x4(rb, sbBHI + ro);
                bh[2 * ni][0] = rb[0]; bh[2 * ni][1] = rb[2];
                bh[2 * ni + 1][0] = rb[1]; bh[2 * ni + 1][1] = rb[3];
                ldm_x4(rb, sbBLO + ro);
                bl[2 * ni][0] = rb[0]; bl[2 * ni][1] = rb[2];
                bl[2 * ni + 1][0] = rb[1]; bl[2 * ni + 1][1] = rb[3];
            }
            #pragma unroll
            for (int mi = 0; mi < 2; mi++)
                #pragma unroll
                for (int nf = 0; nf < 8; nf++)
                    mma_fp16(acc[mi][nf], ah[mi], bh[nf][0], bh[nf][1]);
            #pragma unroll
            for (int mi = 0; mi < 2; mi++)
                #pragma unroll
                for (int nf = 0; nf < 8; nf++)
                    mma_fp16(acc[mi][nf], ah[mi], bl[nf][0], bl[nf][1]);
        }
        __syncthreads();
    }

    // Epilogue: frags -> smem stage (pad 132) -> coalesced global stores with bias
    float* stage = (float*)(sm + SMG_BASE);
    {
        const int g = lane >> 2, t4 = lane & 3;
        #pragma unroll
        for (int mi = 0; mi < 2; mi++)
            #pragma unroll
            for (int nf = 0; nf < 8; nf++) {
                int col = n0w + nf * 8 + 2 * t4;
                float* p0 = &stage[(m0w + mi * 16 + g) * 132 + col];
                float* p1 = &stage[(m0w + mi * 16 + g + 8) * 132 + col];
                p0[0] = acc[mi][nf][0]; p0[1] = acc[mi][nf][1];
                p1[0] = acc[mi][nf][2]; p1[1] = acc[mi][nf][3];
            }
    }
    __syncthreads();
    {
        const int col = tid & 127;
        const float bcol = biass[col];
        #pragma unroll 4
        for (int it = 0; it < 64; it++) {
            int r = it * 2 + (tid >> 7);
            C[(size_t)(crow0 + r) * G3E + n0 + col] = stage[r * 132 + col] + bcol;
        }
    }
}

// =================================================================================
__device__ __forceinline__ float sigmf(float x) {
    return 1.0f / (1.0f + __expf(-x));
}

// ---------------------------------------------------------------------------------
// Encoder bidirectional GRU scan — f32x2 dot + next-step global prefetch.
// ---------------------------------------------------------------------------------
__global__ __launch_bounds__(384, 1) void enc_scan(
    const float* __restrict__ Whh_f, const float* __restrict__ bhh_f,
    const float* __restrict__ Whh_b, const float* __restrict__ bhh_b,
    const float* __restrict__ enc_init)
{
    const int j = threadIdx.x;
    const int dir = blockIdx.x >> 7;
    const int b = blockIdx.x & 127;
    const float* Whh = dir ? Whh_b : Whh_f;
    const float* bhh = dir ? bhh_b : bhh_f;
    const float* xp = dir ? g_xpb : g_xpf;

    unsigned long long w2[64];
    {
        const unsigned long long* wr = (const unsigned long long*)(Whh + j * 128);
        #pragma unroll
        for (int k = 0; k < 64; k++) w2[k] = wr[k];
    }
    const float bh = bhh[j];

    __shared__ __align__(16) float h_s[128];
    __shared__ float hh_s[384];
    if (j < 128) h_s[j] = enc_init[dir * 128 + j];
    __syncthreads();

    const ulonglong2* h2v = (const ulonglong2*)h_s;

    float pr = 0.f, pz = 0.f, pn = 0.f;
    if (j < 128) {
        const float* xr = xp + (size_t)b * G3E;
        pr = xr[j]; pz = xr[128 + j]; pn = xr[256 + j];
    }

    for (int t = 0; t < T_STEPS; t++) {
        // prefetch next timestep's projected inputs (hidden behind dot + barriers)
        float npr = 0.f, npz = 0.f, npn = 0.f;
        if (t + 1 < T_STEPS && j < 128) {
            const float* xr = xp + ((size_t)(t + 1) * BATCH + b) * G3E;
            npr = xr[j]; npz = xr[128 + j]; npn = xr[256 + j];
        }

        unsigned long long a01 = 0ull, a23 = 0ull;
        #pragma unroll
        for (int kk = 0; kk < 32; kk++) {
            ulonglong2 hv = h2v[kk];
            FMA2(a01, w2[2 * kk + 0], hv.x);
            FMA2(a23, w2[2 * kk + 1], hv.y);
        }
        hh_s[j] = bh + (sum2(a01) + sum2(a23));
        __syncthreads();

        if (j < 128) {
            float r = sigmf(pr + hh_s[j]);
            float z = sigmf(pz + hh_s[128 + j]);
            float n = tanhf(pn + r * hh_s[256 + j]);
            float h = (1.f - z) * n + z * h_s[j];
            h_s[j] = h;
            float gc = fminf(fmaxf(h, -CLIPV), CLIPV);
            int tt = dir ? (T_STEPS - 1 - t) : t;
            g_g[((size_t)tt * BATCH + b) * (2 * EDIM) + dir * EDIM + j] = gc;
        }
        __syncthreads();
        pr = npr; pz = npz; pn = npn;
    }
}

// ---------------------------------------------------------------------------------
// Controller GRU + latent sample + spike/calcium generator — f32x2 + prefetch.
// ---------------------------------------------------------------------------------
#define CTRL_SMEM_FLOATS 40832
#define CTRL_SMEM_BYTES  (CTRL_SMEM_FLOATS * 4)

__global__ __launch_bounds__(384, 1) void ctrl_scan(
    const float* __restrict__ factors, const float* __restrict__ eps,
    const float* __restrict__ Whh, const float* __restrict__ bhh,
    const float* __restrict__ cinit,
    const float* __restrict__ W_mu, const float* __restrict__ b_mu,
    const float* __restrict__ W_lv, const float* __restrict__ b_lv,
    const float* __restrict__ W_spk, const float* __restrict__ b_spk,
    const float* __restrict__ gain_p, const float* __restrict__ biasp_p,
    const float* __restrict__ logtau_p,
    float* __restrict__ out)
{
    extern __shared__ __align__(16) float smf[];
    float* wml  = smf;            // 128 x 132
    float* wspk = smf + 16896;    // 300 x 76
    float* h_s  = smf + 39696;    // 128
    float* hh_s = smf + 39824;    // 384
    float* mlv  = smf + 40208;    // 128
    float* gen  = smf + 40336;    // 68
    float* bml  = smf + 40404;    // 128
    float* bsp  = smf + 40532;    // 300

    const int j = threadIdx.x;
    const int b = blockIdx.x;

    unsigned long long w2[64];
    {
        const unsigned long long* wr = (const unsigned long long*)(Whh + j * 128);
        #pragma unroll
        for (int k = 0; k < 64; k++) w2[k] = wr[k];
    }
    const float bh = bhh[j];

    for (int idx = j; idx < 128 * 128; idx += 384) {
        int r = idx >> 7, k = idx & 127;
        wml[r * 132 + k] = (r < 64) ? W_mu[r * 128 + k] : W_lv[(r - 64) * 128 + k];
    }
    for (int idx = j; idx < 300 * 68; idx += 384) {
        int r = idx / 68, k = idx - r * 68;
        wspk[r * 76 + k] = W_spk[idx];
    }
    if (j < 128) { bml[j] = (j < 64) ? b_mu[j] : b_lv[j - 64]; h_s[j] = cinit[j]; }
    if (j < 300) bsp[j] = b_spk[j];

    const float gain  = gain_p[0];
    const float biasp = biasp_p[0];
    const float decay = 1.f - expf(-logtau_p[0]);
    float cal = 0.f;
    __syncthreads();

    const ulonglong2* h2v = (const ulonglong2*)h_s;
    const ulonglong2* g2v = (const ulonglong2*)gen;

    float pr = 0.f, pz = 0.f, pn = 0.f, ev = 0.f, fv = 0.f;
    {
        const float* cpr = g_cp + (size_t)b * G3E;
        if (j < 128) { pr = cpr[j]; pz = cpr[128 + j]; pn = cpr[256 + j]; }
        if (j < UDIM) ev = eps[(size_t)b * UDIM + j];
        else if (j < UDIM + FDIM) fv = factors[(size_t)b * FDIM + (j - UDIM)];
    }

    for (int t = 0; t < T_STEPS; t++) {
        size_t row = (size_t)t * BATCH + b;

        // prefetch next timestep inputs
        float npr = 0.f, npz = 0.f, npn = 0.f, nev = 0.f, nfv = 0.f;
        if (t + 1 < T_STEPS) {
            size_t nrow = row + BATCH;
            const float* cpr = g_cp + nrow * G3E;
            if (j < 128) { npr = cpr[j]; npz = cpr[128 + j]; npn = cpr[256 + j]; }
            if (j < UDIM) nev = eps[nrow * UDIM + j];
            else if (j < UDIM + FDIM) nfv = factors[nrow * FDIM + (j - UDIM)];
        }

        // hh = Whh @ h + bhh (packed)
        unsigned long long a01 = 0ull, a23 = 0ull;
        #pragma unroll
        for (int kk = 0; kk < 32; kk++) {
            ulonglong2 hv = h2v[kk];
            FMA2(a01, w2[2 * kk + 0], hv.x);
            FMA2(a23, w2[2 * kk + 1], hv.y);
        }
        hh_s[j] = bh + (sum2(a01) + sum2(a23));
        __syncthreads();

        // gates, clip
        if (j < 128) {
            float r = sigmf(pr + hh_s[j]);
            float z = sigmf(pz + hh_s[128 + j]);
            float n = tanhf(pn + r * hh_s[256 + j]);
            float h = (1.f - z) * n + z * h_s[j];
            h = fminf(fmaxf(h, -CLIPV), CLIPV);
            h_s[j] = h;
        }
        __syncthreads();

        // mu (j<64) / lv (64<=j<128), packed
        if (j < 128) {
            unsigned long long m01 = 0ull, m23 = 0ull;
            const ulonglong2* wr2 = (const ulonglong2*)&wml[j * 132];
            #pragma unroll
            for (int kk = 0; kk < 32; kk++) {
                ulonglong2 wv = wr2[kk];
                ulonglong2 hv = h2v[kk];
                FMA2(m01, wv.x, hv.x);
                FMA2(m23, wv.y, hv.y);
            }
            mlv[j] = bml[j] + (sum2(m01) + sum2(m23));
        }
        __syncthreads();

        // u = mu + exp(0.5 lv) * eps ; gen = [u, f]
        if (j < UDIM) gen[j] = mlv[j] + __expf(0.5f * mlv[UDIM + j]) * ev;
        else if (j < UDIM + FDIM) gen[j] = fv;
        __syncthreads();

        // spike + calcium, packed
        if (j < NIN) {
            unsigned long long s01 = 0ull, s23 = 0ull;
            const ulonglong2* wr2 = (const ulonglong2*)&wspk[j * 76];
            #pragma unroll
            for (int kk = 0; kk < 17; kk++) {
                ulonglong2 wv = wr2[kk];
                ulonglong2 gv = g2v[kk];
                FMA2(s01, wv.x, gv.x);
                FMA2(s23, wv.y, gv.y);
            }
            float logit = bsp[j] + (sum2(s01) + sum2(s23));
            float spike = fmaxf(__expf(logit) - 1.f, 0.f);
            cal = cal * decay + gain * spike + biasp;
            out[row * NIN + j] = cal;
        }
        pr = npr; pz = npz; pn = npn; ev = nev; fv = nfv;
    }
}

// ---------------------------------------------------------------------------------
extern "C" void kernel_launch(void* const* d_in, const int* in_sizes, int n_in,
                              void* d_out, int out_size)
{
    (void)in_sizes; (void)n_in; (void)out_size;
    const float* x       = (const float*)d_in[0];
    const float* factors = (const float*)d_in[1];
    const float* eps     = (const float*)d_in[2];
    const float* eWihf   = (const float*)d_in[3];
    const float* eWhhf   = (const float*)d_in[4];
    const float* ebihf   = (const float*)d_in[5];
    const float* ebhhf   = (const float*)d_in[6];
    const float* eWihb   = (const float*)d_in[7];
    const float* eWhhb   = (const float*)d_in[8];
    const float* ebihb   = (const float*)d_in[9];
    const float* ebhhb   = (const float*)d_in[10];
    const float* einit   = (const float*)d_in[11];
    const float* cWih    = (const float*)d_in[12];
    const float* cWhh    = (const float*)d_in[13];
    const float* cbih    = (const float*)d_in[14];
    const float* cbhh    = (const float*)d_in[15];
    const float* cinit   = (const float*)d_in[16];
    const float* Wmu     = (const float*)d_in[17];
    const float* bmu     = (const float*)d_in[18];
    const float* Wlv     = (const float*)d_in[19];
    const float* blv     = (const float*)d_in[20];
    const float* Wspk    = (const float*)d_in[21];
    const float* bspk    = (const float*)d_in[22];
    const float* gain    = (const float*)d_in[23];
    const float* bp      = (const float*)d_in[24];
    const float* ltau    = (const float*)d_in[25];
    float* out = (float*)d_out;

    float *xpf, *xpb, *gg, *cp;
    cudaGetSymbolAddress((void**)&xpf, g_xpf);
    cudaGetSymbolAddress((void**)&xpb, g_xpb);
    cudaGetSymbolAddress((void**)&gg,  g_g);
    cudaGetSymbolAddress((void**)&cp,  g_cp);

    uint2 *xh, *gh, *wfh, *wfl, *wbh, *wbl, *wch, *wcl;
    cudaGetSymbolAddress((void**)&xh, g_xh);
    cudaGetSymbolAddress((void**)&gh, g_gh);
    cudaGetSymbolAddress((void**)&wfh, g_wfh); cudaGetSymbolAddress((void**)&wfl, g_wfl);
    cudaGetSymbolAddress((void**)&wbh, g_wbh); cudaGetSymbolAddress((void**)&wbl, g_wbl);
    cudaGetSymbolAddress((void**)&wch, g_wch); cudaGetSymbolAddress((void**)&wcl, g_wcl);

    cudaFuncSetAttribute(gemm_mma, cudaFuncAttributeMaxDynamicSharedMemorySize, GEMM_SMEM);
    cudaFuncSetAttribute(ctrl_scan, cudaFuncAttributeMaxDynamicSharedMemorySize, CTRL_SMEM_BYTES);

    dim3 gemm_grid(T_STEPS, G3E / 128);

    // conversions + GEMMs (gemm_f placed 4th so the ncu capture slot lands on it)
    conv_half<<<(XN4 + 255) / 256, 256>>>((const float4*)x, xh, XN4);
    conv_half_split<<<(WFN4 + 255) / 256, 256>>>((const float4*)eWihf, wfh, wfl, WFN4);
    conv_half_split<<<(WFN4 + 255) / 256, 256>>>((const float4*)eWihb, wbh, wbl, WFN4);
    gemm_mma<<<gemm_grid, 256, GEMM_SMEM>>>(xh, NIN, nullptr, 0, wfh, wfl, ebihf, xpf, 0);
    conv_half_split<<<(WCN4 + 255) / 256, 256>>>((const float4*)cWih, wch, wcl, WCN4);
    gemm_mma<<<gemm_grid, 256, GEMM_SMEM>>>(xh, NIN, nullptr, 0, wbh, wbl, ebihb, xpb, 1);

    // bidirectional encoder scan -> g (clipped, original timeline)
    enc_scan<<<256, 384>>>(eWhhf, ebhhf, eWhhb, ebhhb, einit);

    // convert g, then cp = [g, x] @ ctrl_Wih^T + b
    conv_half<<<(GN4 + 255) / 256, 256>>>((const float4*)gg, gh, GN4);
    gemm_mma<<<gemm_grid, 256, GEMM_SMEM>>>(gh, 2 * EDIM, xh, NIN, wch, wcl, cbih, cp, 0);

    // controller scan -> calcium (d_out)
    ctrl_scan<<<128, 384, CTRL_SMEM_BYTES>>>(factors, eps, cWhh, cbhh, cinit,
                                             Wmu, bmu, Wlv, blv, Wspk, bspk,
                                             gain, bp, ltau, out);
}